// round 16
// baseline (speedup 1.0000x reference)
#include <cuda_runtime.h>
#include <cstdint>

// PointConv: B=32, C=64, H=W=64, KH=KW=2 -> L=1024, n=256.
// Per l: D[p, b] = sum_k W[l][k][p] * patch[b][k] + bias[p, l]
// fp32 via 3-term bf16 split on mma.sync.m16n8k16.
// R16: persistent CTAs (grid=296) + atomic task queue; cross-task pipelining
//      (next patch cp.async during mainloop, W lookahead bridges tasks).
//      Fix vs R15: patch staging is 32 KB -> SMEM_TOTAL 98304.

#define HH 64
#define CC 64
#define NN 256
#define LL 1024

#define KSTAGE 16
#define NSTG   16
#define GRID   296

#define OFF_F  0                    // frag stream: 2 bufs x 32768
#define OFF_PB 65536                // patch fp32 staging: 16 x 2048 B = 32768
#define SMEM_TOTAL 98304

__device__ int g_ctr;

__device__ __forceinline__ uint32_t cvt2(float lo, float hi) {  // pack {lo=low16, hi=high16}
    uint32_t r;
    asm("cvt.rn.bf16x2.f32 %0, %1, %2;" : "=r"(r) : "f"(hi), "f"(lo));
    return r;
}
__device__ __forceinline__ float lo_f(uint32_t p) { return __uint_as_float(p << 16); }
__device__ __forceinline__ float hi_f(uint32_t p) { return __uint_as_float(p & 0xffff0000u); }

__device__ __forceinline__ void cp_async8(uint32_t dst, const void* src) {
    asm volatile("cp.async.ca.shared.global [%0], [%1], 8;" :: "r"(dst), "l"(src));
}
__device__ __forceinline__ void mma_bf16(float* d, const uint32_t* a, uint32_t b0, uint32_t b1) {
    asm volatile(
        "mma.sync.aligned.m16n8k16.row.col.f32.bf16.bf16.f32 "
        "{%0,%1,%2,%3}, {%4,%5,%6,%7}, {%8,%9}, {%0,%1,%2,%3};"
        : "+f"(d[0]), "+f"(d[1]), "+f"(d[2]), "+f"(d[3])
        : "r"(a[0]), "r"(a[1]), "r"(a[2]), "r"(a[3]), "r"(b0), "r"(b1));
}

// write one (b, k-even) bf16 hi/mid pair into a frag-stream buffer
__device__ __forceinline__ void frag_store(char* fb, int b, int k, float v0, float v1) {
    const int nt = b >> 3, bq = b & 7;
    const int s  = k >> 4;
    const int kk = k & 15;
    const int t  = (kk >> 1) & 3;
    const int hi8 = (kk >= 8) ? 1 : 0;
    const uint32_t hp = cvt2(v0, v1);
    const uint32_t mp = cvt2(v0 - lo_f(hp), v1 - hi_f(hp));
    char* dst = fb + (s * 4 + nt) * 512 + (bq * 4 + t) * 16;
    *reinterpret_cast<uint32_t*>(dst + hi8 * 4)     = hp;
    *reinterpret_cast<uint32_t*>(dst + 8 + hi8 * 4) = mp;
}

__global__ void init_ctr() { g_ctr = GRID; }

__global__ void __launch_bounds__(256, 2)
pointconv_mma(const float* __restrict__ x,
              const float* __restrict__ w,
              const float* __restrict__ bias,
              float* __restrict__ out)
{
    extern __shared__ char smem[];
    __shared__ int s_next;
    const uint32_t sbase = (uint32_t)__cvta_generic_to_shared(smem);
    const int tid  = threadIdx.x;
    const int wid  = tid >> 5;                  // 0..7
    const int lane = tid & 31;

    const int wbase = wid * 32;                 // warp's p slice
    const int g = lane >> 2;
    const int c = (lane & 3) * 2;
    const int pb = tid & 31;                    // patch b handled by this thread
    const int cg = tid >> 5;

    int cur = blockIdx.x;
    int buf = 0;

    // ---- first-task prologue: direct gather -> fbuf[0] ----
    {
        const int ph = cur >> 5, pw = cur & 31;
        char* fb = smem + OFF_F;
        #pragma unroll
        for (int ci = 0; ci < 8; ci++) {
            const int cc = cg * 8 + ci;
            #pragma unroll
            for (int kh = 0; kh < 2; kh++) {
                const float2 v = *reinterpret_cast<const float2*>(
                    x + (size_t)(((pb * CC + cc) * HH + 2 * ph + kh) * HH + 2 * pw));
                frag_store(fb, pb, cc * 4 + kh * 2, v.x, v.y);
            }
        }
    }

    // W raw fragment loads, stage 0 of first task
    float raw[2][8];
    {
        const float* lb = w + (size_t)cur * (NN * NN) + (size_t)c * NN + wbase + g;
        #pragma unroll
        for (int pt = 0; pt < 2; pt++) {
            const float* bp = lb + pt * 16;
            raw[pt][0] = bp[0];        raw[pt][1] = bp[NN];
            raw[pt][2] = bp[8];        raw[pt][3] = bp[NN + 8];
            raw[pt][4] = bp[8 * NN];   raw[pt][5] = bp[9 * NN];
            raw[pt][6] = bp[8 * NN + 8]; raw[pt][7] = bp[9 * NN + 8];
        }
    }
    float raw2[2][8];   // second raw bank (ping-pong)

    // ---- persistent task loop ----
    while (cur < LL) {
        if (tid == 0) s_next = atomicAdd(&g_ctr, 1);
        __syncthreads();                        // broadcast next; fbuf[buf] ready
        const int next = s_next;
        const int ph = cur >> 5, pw = cur & 31;
        const float* __restrict__ wl = w + (size_t)cur * (NN * NN);
        const float* lbase  = wl + (size_t)c * NN + wbase + g;
        const float* lbnext = w + (size_t)next * (NN * NN) + (size_t)c * NN + wbase + g;

        // stream next task's patch (fp32) into staging via cp.async
        if (next < LL) {
            const int nph = next >> 5, npw = next & 31;
            #pragma unroll
            for (int ci = 0; ci < 8; ci++) {
                const int cc = cg * 8 + ci;
                #pragma unroll
                for (int kh = 0; kh < 2; kh++) {
                    const int j = ci * 2 + kh;
                    cp_async8(sbase + OFF_PB + j * 2048 + tid * 8,
                              x + (size_t)(((pb * CC + cc) * HH + 2 * nph + kh) * HH + 2 * npw));
                }
            }
        }
        asm volatile("cp.async.commit_group;" ::: "memory");

        float d[2][4][4];
        #pragma unroll
        for (int i = 0; i < 2; i++)
            #pragma unroll
            for (int j = 0; j < 4; j++)
                #pragma unroll
                for (int r = 0; r < 4; r++) d[i][j][r] = 0.0f;

        const char* fb = smem + OFF_F + buf * 32768;

        // ---- mainloop: barrier-free, register-direct A fragments ----
        #pragma unroll 1
        for (int s = 0; s < NSTG; s++) {
            float (*rc)[8] = (s & 1) ? raw2 : raw;
            float (*rn)[8] = (s & 1) ? raw : raw2;

            uint32_t ah[2][4], am[2][4];
            #pragma unroll
            for (int pt = 0; pt < 2; pt++)
                #pragma unroll
                for (int j = 0; j < 4; j++) {
                    const float v0 = rc[pt][j * 2];
                    const float v1 = rc[pt][j * 2 + 1];
                    const uint32_t h = cvt2(v0, v1);
                    ah[pt][j] = h;
                    am[pt][j] = cvt2(v0 - lo_f(h), v1 - hi_f(h));
                }

            // next-stage raw loads (stage 15 bridges to next task)
            const bool bridge = (s == NSTG - 1);
            if (!bridge || next < LL) {
                const float* sb = bridge ? lbnext
                                         : lbase + (size_t)(s + 1) * KSTAGE * NN;
                #pragma unroll
                for (int pt = 0; pt < 2; pt++) {
                    const float* bp = sb + pt * 16;
                    rn[pt][0] = bp[0];        rn[pt][1] = bp[NN];
                    rn[pt][2] = bp[8];        rn[pt][3] = bp[NN + 8];
                    rn[pt][4] = bp[8 * NN];   rn[pt][5] = bp[9 * NN];
                    rn[pt][6] = bp[8 * NN + 8]; rn[pt][7] = bp[9 * NN + 8];
                }
            }

            uint4 bf[4];
            #pragma unroll
            for (int nt = 0; nt < 4; nt++)
                bf[nt] = *reinterpret_cast<const uint4*>(fb + (s * 4 + nt) * 512 + lane * 16);

            #pragma unroll
            for (int pt = 0; pt < 2; pt++)
                #pragma unroll
                for (int nt = 0; nt < 4; nt++) {
                    mma_bf16(d[pt][nt], ah[pt], bf[nt].x, bf[nt].y);   // hi * hi
                    mma_bf16(d[pt][nt], ah[pt], bf[nt].z, bf[nt].w);   // hi * mid
                    mma_bf16(d[pt][nt], am[pt], bf[nt].x, bf[nt].y);   // mid * hi
                }
        }

        // ---- epilogue: bias + scatter (fire-and-forget) ----
        #pragma unroll
        for (int pt = 0; pt < 2; pt++) {
            const int p0 = wbase + pt * 16 + (lane >> 2);
            const int p1 = p0 + 8;
            const float bv0 = bias[p0 * LL + cur];
            const float bv1 = bias[p1 * LL + cur];
            const int c0 = p0 >> 2, kh0 = (p0 >> 1) & 1, kw0 = p0 & 1;
            const int c1 = p1 >> 2, kh1 = (p1 >> 1) & 1, kw1 = p1 & 1;
            #pragma unroll
            for (int nt = 0; nt < 4; nt++) {
                const int b = nt * 8 + 2 * (lane & 3);
                const size_t o0 = (size_t)(((b * CC + c0) * HH + 2 * ph + kh0) * HH + 2 * pw + kw0);
                const size_t o1 = (size_t)(((b * CC + c1) * HH + 2 * ph + kh1) * HH + 2 * pw + kw1);
                const size_t bs = (size_t)CC * HH * HH;
                out[o0]      = d[pt][nt][0] + bv0;
                out[o0 + bs] = d[pt][nt][1] + bv0;
                out[o1]      = d[pt][nt][2] + bv1;
                out[o1 + bs] = d[pt][nt][3] + bv1;
            }
        }

        // ---- convert staged patch -> other frag buffer ----
        if (next < LL) {
            asm volatile("cp.async.wait_group 0;" ::: "memory");
            __syncthreads();
            char* fb2 = smem + OFF_F + (buf ^ 1) * 32768;
            #pragma unroll
            for (int ci = 0; ci < 8; ci++) {
                #pragma unroll
                for (int kh = 0; kh < 2; kh++) {
                    const int j = ci * 2 + kh;
                    const float2 v = *reinterpret_cast<const float2*>(
                        smem + OFF_PB + j * 2048 + tid * 8);
                    frag_store(fb2, pb, (cg * 8 + ci) * 4 + kh * 2, v.x, v.y);
                }
            }
        }

        cur = next;
        buf ^= 1;
    }
}

extern "C" void kernel_launch(void* const* d_in, const int* in_sizes, int n_in,
                              void* d_out, int out_size)
{
    const float* x    = (const float*)d_in[0];
    const float* w    = (const float*)d_in[1];
    const float* bias = (const float*)d_in[2];
    float* out        = (float*)d_out;

    init_ctr<<<1, 1>>>();
    cudaFuncSetAttribute(pointconv_mma,
                         cudaFuncAttributeMaxDynamicSharedMemorySize, SMEM_TOTAL);
    pointconv_mma<<<GRID, 256, SMEM_TOTAL>>>(x, w, bias, out);
}